// round 6
// baseline (speedup 1.0000x reference)
#include <cuda_runtime.h>

#define SEQ    4096
#define DM     1024
#define ZIPD   256
#define HEADS  8
#define DK     32      // ZIP / HEADS
#define DV     128     // DM / HEADS

// ---------------- scratch (static device globals; no allocation) ----------------
__device__ float g_qp[SEQ * ZIPD];   // Q' = q @ w_q^T + b_q
__device__ float g_kp[SEQ * ZIPD];   // K' = k @ w_k^T + b_k
__device__ float g_vr[SEQ * ZIPD];   // Vr = v @ w_v_r^T + b_v_r
__device__ float g_v [SEQ * DM];     // V  = Vr @ w_v_l^T + b_v_l

// =====================================================================
// Generic tiled fp32 GEMM body:  Y[M,N] = X[M,K] @ W[N,K]^T + B[N]
// BM=BN=64, BK=16, 256 threads, 4x4 per-thread tile.
// =====================================================================
__device__ __forceinline__ void gemm_body(const float* __restrict__ X,
                                          const float* __restrict__ W,
                                          const float* __restrict__ B,
                                          float* __restrict__ Y,
                                          int N, int K)
{
    __shared__ float Xs[16][68];   // [k][m], padded
    __shared__ float Ws[16][68];   // [k][n], padded

    const int tid = threadIdx.x;
    const int tx  = tid & 15;       // 0..15 -> n
    const int ty  = tid >> 4;       // 0..15 -> m
    const int m0  = blockIdx.y * 64;
    const int n0  = blockIdx.x * 64;
    const int lrow = tid >> 2;      // 0..63
    const int lc4  = (tid & 3) * 4; // 0,4,8,12

    float acc[4][4];
#pragma unroll
    for (int i = 0; i < 4; ++i)
#pragma unroll
        for (int j = 0; j < 4; ++j) acc[i][j] = 0.f;

    for (int kk0 = 0; kk0 < K; kk0 += 16) {
        float4 xa = *(const float4*)&X[(m0 + lrow) * K + kk0 + lc4];
        float4 wa = *(const float4*)&W[(n0 + lrow) * K + kk0 + lc4];
        __syncthreads();
        Xs[lc4 + 0][lrow] = xa.x; Xs[lc4 + 1][lrow] = xa.y;
        Xs[lc4 + 2][lrow] = xa.z; Xs[lc4 + 3][lrow] = xa.w;
        Ws[lc4 + 0][lrow] = wa.x; Ws[lc4 + 1][lrow] = wa.y;
        Ws[lc4 + 2][lrow] = wa.z; Ws[lc4 + 3][lrow] = wa.w;
        __syncthreads();

#pragma unroll
        for (int kk = 0; kk < 16; ++kk) {
            float4 xm4 = *(const float4*)&Xs[kk][ty * 4];
            float4 wn4 = *(const float4*)&Ws[kk][tx * 4];
            float xm[4] = {xm4.x, xm4.y, xm4.z, xm4.w};
            float wn[4] = {wn4.x, wn4.y, wn4.z, wn4.w};
#pragma unroll
            for (int i = 0; i < 4; ++i)
#pragma unroll
                for (int j = 0; j < 4; ++j)
                    acc[i][j] += xm[i] * wn[j];
        }
    }

    float4 bb = *(const float4*)&B[n0 + tx * 4];
#pragma unroll
    for (int i = 0; i < 4; ++i) {
        int row = m0 + ty * 4 + i;
        float4 o = make_float4(acc[i][0] + bb.x, acc[i][1] + bb.y,
                               acc[i][2] + bb.z, acc[i][3] + bb.w);
        *(float4*)&Y[row * N + n0 + tx * 4] = o;
    }
}

// Three low-rank projections batched over blockIdx.z.
__global__ __launch_bounds__(256) void proj3_kernel(
    const float* __restrict__ q,  const float* __restrict__ k,  const float* __restrict__ v,
    const float* __restrict__ wq, const float* __restrict__ wk, const float* __restrict__ wvr,
    const float* __restrict__ bq, const float* __restrict__ bk, const float* __restrict__ bvr)
{
    const float* X; const float* W; const float* B; float* Y;
    if (blockIdx.z == 0)      { X = q; W = wq;  B = bq;  Y = g_qp; }
    else if (blockIdx.z == 1) { X = k; W = wk;  B = bk;  Y = g_kp; }
    else                      { X = v; W = wvr; B = bvr; Y = g_vr; }
    gemm_body(X, W, B, Y, ZIPD, DM);
}

// V up-projection: g_v = g_vr @ w_v_l^T + b_v_l
__global__ __launch_bounds__(256) void projv_kernel(const float* __restrict__ wvl,
                                                    const float* __restrict__ bvl)
{
    gemm_body(g_vr, wvl, bvl, g_v, DM, ZIPD);
}

// =====================================================================
// Flash attention, fp32, non-causal full softmax, NO 1/sqrt(dk) scaling.
// Grid: (SEQ/64 q-tiles, HEADS). Block: 256 threads = 8 warps.
// Warp w owns q-rows [8w, 8w+8). Bq=64, Bk=64, dk=32, dv=128.
// Lane layout: QK -> lane owns k-cols {2l, 2l+1}; PV -> lane owns dv-cols 4l..4l+3.
// =====================================================================
#define QS_LD  36
#define KST_LD 66
#define FLASH_SMEM_FLOATS (64*QS_LD + 32*KST_LD + 64*128 + 8*8*64)
#define FLASH_SMEM_BYTES  (FLASH_SMEM_FLOATS * 4)

__global__ __launch_bounds__(256) void flash_kernel(float* __restrict__ out)
{
    extern __shared__ float sm[];
    float* Qs  = sm;                       // [64][36]
    float* Kst = Qs  + 64 * QS_LD;         // [32][66]  (K transposed: [d][row])
    float* Vs  = Kst + 32 * KST_LD;        // [64][128]
    float* Ps  = Vs  + 64 * 128;           // [8 warps][8 rows][64]

    const int tid  = threadIdx.x;
    const int lane = tid & 31;
    const int warp = tid >> 5;
    const int h    = blockIdx.y;
    const int s0q  = blockIdx.x * 64;
    const int r0   = warp * 8;
    float* Psw = Ps + warp * (8 * 64);

    // ---- load Q tile once ----
    {
        const int row = tid >> 3;          // 0..31
        const int d4  = (tid & 7) * 4;     // 0..28
#pragma unroll
        for (int p = 0; p < 2; ++p) {
            int rr = p * 32 + row;
            float4 qv = *(const float4*)&g_qp[(s0q + rr) * ZIPD + h * DK + d4];
            *(float4*)&Qs[rr * QS_LD + d4] = qv;
        }
    }

    float O[8][4];
    float m_r[8], l_r[8];
#pragma unroll
    for (int r = 0; r < 8; ++r) {
        m_r[r] = -1e30f; l_r[r] = 0.f;
        O[r][0] = O[r][1] = O[r][2] = O[r][3] = 0.f;
    }

    for (int t = 0; t < SEQ / 64; ++t) {
        const int s0k = t * 64;
        __syncthreads();   // previous tile fully consumed (also covers Qs on t=0)

        // ---- load K tile transposed: Kst[d][row] ----
        {
            const int row = tid >> 3;
            const int d4  = (tid & 7) * 4;
#pragma unroll
            for (int p = 0; p < 2; ++p) {
                int rr = p * 32 + row;
                float4 kv = *(const float4*)&g_kp[(s0k + rr) * ZIPD + h * DK + d4];
                Kst[(d4 + 0) * KST_LD + rr] = kv.x;
                Kst[(d4 + 1) * KST_LD + rr] = kv.y;
                Kst[(d4 + 2) * KST_LD + rr] = kv.z;
                Kst[(d4 + 3) * KST_LD + rr] = kv.w;
            }
        }
        // ---- load V tile [64][128] ----
#pragma unroll
        for (int i = 0; i < 8; ++i) {
            int f   = tid + 256 * i;     // 0..2047 float4s
            int row = f >> 5;
            int c4  = (f & 31) * 4;
            *(float4*)&Vs[row * 128 + c4] =
                *(const float4*)&g_v[(s0k + row) * DM + h * DV + c4];
        }
        __syncthreads();

        // ---- S = Q K^T : 8 rows x 2 k-cols per lane ----
        float s0[8], s1[8];
#pragma unroll
        for (int r = 0; r < 8; ++r) { s0[r] = 0.f; s1[r] = 0.f; }
#pragma unroll
        for (int d4 = 0; d4 < 8; ++d4) {
            float2 k0 = *(const float2*)&Kst[(4 * d4 + 0) * KST_LD + 2 * lane];
            float2 k1 = *(const float2*)&Kst[(4 * d4 + 1) * KST_LD + 2 * lane];
            float2 k2 = *(const float2*)&Kst[(4 * d4 + 2) * KST_LD + 2 * lane];
            float2 k3 = *(const float2*)&Kst[(4 * d4 + 3) * KST_LD + 2 * lane];
#pragma unroll
            for (int r = 0; r < 8; ++r) {
                float4 qv = *(const float4*)&Qs[(r0 + r) * QS_LD + 4 * d4];
                s0[r] += qv.x * k0.x + qv.y * k1.x + qv.z * k2.x + qv.w * k3.x;
                s1[r] += qv.x * k0.y + qv.y * k1.y + qv.z * k2.y + qv.w * k3.y;
            }
        }

        // ---- online softmax per row (warp-local) ----
#pragma unroll
        for (int r = 0; r < 8; ++r) {
            float mx = fmaxf(s0[r], s1[r]);
#pragma unroll
            for (int off = 16; off > 0; off >>= 1)
                mx = fmaxf(mx, __shfl_xor_sync(0xffffffffu, mx, off));
            float mnew  = fmaxf(m_r[r], mx);
            float scale = __expf(m_r[r] - mnew);
            float p0 = __expf(s0[r] - mnew);
            float p1 = __expf(s1[r] - mnew);
            float rs = p0 + p1;
#pragma unroll
            for (int off = 16; off > 0; off >>= 1)
                rs += __shfl_xor_sync(0xffffffffu, rs, off);
            l_r[r] = l_r[r] * scale + rs;
            m_r[r] = mnew;
            O[r][0] *= scale; O[r][1] *= scale;
            O[r][2] *= scale; O[r][3] *= scale;
            *(float2*)&Psw[r * 64 + 2 * lane] = make_float2(p0, p1);
        }
        __syncwarp();   // Psw is warp-private; make cross-lane stores visible

        // ---- O += P @ V : lane owns dv-cols 4l..4l+3 ----
#pragma unroll
        for (int k4 = 0; k4 < 16; ++k4) {
            float4 v0 = *(const float4*)&Vs[(4 * k4 + 0) * 128 + 4 * lane];
            float4 v1 = *(const float4*)&Vs[(4 * k4 + 1) * 128 + 4 * lane];
            float4 v2 = *(const float4*)&Vs[(4 * k4 + 2) * 128 + 4 * lane];
            float4 v3 = *(const float4*)&Vs[(4 * k4 + 3) * 128 + 4 * lane];
#pragma unroll
            for (int r = 0; r < 8; ++r) {
                float4 p = *(const float4*)&Psw[r * 64 + 4 * k4];
                O[r][0] += p.x * v0.x + p.y * v1.x + p.z * v2.x + p.w * v3.x;
                O[r][1] += p.x * v0.y + p.y * v1.y + p.z * v2.y + p.w * v3.y;
                O[r][2] += p.x * v0.z + p.y * v1.z + p.z * v2.z + p.w * v3.z;
                O[r][3] += p.x * v0.w + p.y * v1.w + p.z * v2.w + p.w * v3.w;
            }
        }
        // next-iteration __syncthreads() fences Psw/Vs reuse
    }

    // ---- epilogue: normalize and store ----
#pragma unroll
    for (int r = 0; r < 8; ++r) {
        float inv = 1.0f / l_r[r];
        int row = s0q + r0 + r;
        float4 o = make_float4(O[r][0] * inv, O[r][1] * inv,
                               O[r][2] * inv, O[r][3] * inv);
        *(float4*)&out[row * DM + h * DV + 4 * lane] = o;
    }
}

// =====================================================================
// launch
// =====================================================================
extern "C" void kernel_launch(void* const* d_in, const int* in_sizes, int n_in,
                              void* d_out, int out_size)
{
    (void)in_sizes; (void)n_in; (void)out_size;
    const float* q   = (const float*)d_in[0];
    const float* k   = (const float*)d_in[1];
    const float* v   = (const float*)d_in[2];
    const float* wq  = (const float*)d_in[3];
    const float* bq  = (const float*)d_in[4];
    const float* wk  = (const float*)d_in[5];
    const float* bk  = (const float*)d_in[6];
    const float* wvr = (const float*)d_in[7];
    const float* bvr = (const float*)d_in[8];
    const float* wvl = (const float*)d_in[9];
    const float* bvl = (const float*)d_in[10];
    float* out = (float*)d_out;

    // 1) Q', K', Vr projections (batched over z)
    dim3 g1(ZIPD / 64, SEQ / 64, 3);
    proj3_kernel<<<g1, 256>>>(q, k, v, wq, wk, wvr, bq, bk, bvr);

    // 2) V up-projection
    dim3 g2(DM / 64, SEQ / 64);
    projv_kernel<<<g2, 256>>>(wvl, bvl);

    // 3) flash attention (>48KB dynamic smem -> opt-in; not a stream op, capture-safe)
    cudaFuncSetAttribute(flash_kernel,
                         cudaFuncAttributeMaxDynamicSharedMemorySize,
                         FLASH_SMEM_BYTES);
    dim3 g3(SEQ / 64, HEADS);
    flash_kernel<<<g3, 256, FLASH_SMEM_BYTES>>>(out);
}